// round 16
// baseline (speedup 1.0000x reference)
#include <cuda_runtime.h>

#define NPTS   65536
#define BATCH  2
#define ROWS   (BATCH*NPTS)
#define DIM    35
#define KNN    16
#define CH8    8
#define CH32   32
#define OUTCH  128
#define EPSF   1e-5f

typedef unsigned long long u64;

// packed fp32x2 helpers (FFMA2/FMUL2 — ptxas never emits these from C++)
__device__ __forceinline__ u64 pk2(float lo, float hi) {
    u64 r; asm("mov.b64 %0, {%1, %2};" : "=l"(r) : "f"(lo), "f"(hi)); return r;
}
__device__ __forceinline__ void up2(u64 v, float& lo, float& hi) {
    asm("mov.b64 {%0, %1}, %2;" : "=f"(lo), "=f"(hi) : "l"(v));
}
__device__ __forceinline__ u64 ff2(u64 a, u64 b, u64 c) {
    u64 d; asm("fma.rn.f32x2 %0, %1, %2, %3;" : "=l"(d) : "l"(a), "l"(b), "l"(c)); return d;
}
__device__ __forceinline__ u64 fm2(u64 a, u64 b) {
    u64 d; asm("mul.rn.f32x2 %0, %1, %2;" : "=l"(d) : "l"(a), "l"(b)); return d;
}

// Pass-1 outputs
__device__ __align__(16) float  g_gam[(size_t)ROWS*CH32];  // 16.8 MB, L2-resident
__device__ __align__(16) float4 g_nbr[ROWS];               // {pn.x,pn.y,pn.z,mm}
// center record: {base[0..3]},{base[4..7]},{px,py,pz,em+K0} = 48B/row
__device__ __align__(16) float4 g_ctr[(size_t)ROWS*3];

// ---------------------------------------------------------------------------
// Pass 1: per-row precompute — gam[32], base[8], em', mm, pn. (R15 winner)
// ---------------------------------------------------------------------------
__global__ void __launch_bounds__(128) pass1_kernel(
    const float* __restrict__ feats,
    const float* __restrict__ point_W, const float* __restrict__ point_bn,
    const float* __restrict__ eta_W,   const float* __restrict__ eta_bn,
    const float* __restrict__ mu_W,    const float* __restrict__ mu_bn,
    const float* __restrict__ gamma_W, const float* __restrict__ gamma_bn,
    const float* __restrict__ map_W,   const float* __restrict__ map_bn)
{
    __shared__ __align__(16) float srow[256*DIM + 1];
    __shared__ __align__(16) float sW[DIM*CH32];
    __shared__ __align__(16) float stg[CH32];
    __shared__ __align__(16) float sPA[3*CH8], stp[CH8];
    __shared__ float su[32], sv[32];
    __shared__ float sK0;
    int tid = threadIdx.x;
    int R0  = blockIdx.x * 256;

    const float4* src = (const float4*)feats + ((size_t)R0 * DIM >> 2);
    float4* dst = (float4*)srow;
    for (int i = tid; i < 256*DIM/4; i += 128) dst[i] = src[i];

    float s_map = map_bn[0] * rsqrtf(map_bn[3] + EPSF);
    for (int i = tid; i < DIM*CH32; i += 128) {
        int c = i & 31;
        float sg = gamma_bn[0*CH32+c] * rsqrtf(gamma_bn[3*CH32+c] + EPSF);
        sW[i] = gamma_W[i] * sg;
    }
    if (tid < CH32) {
        int c = tid;
        float sg = gamma_bn[0*CH32+c] * rsqrtf(gamma_bn[3*CH32+c] + EPSF);
        stg[c] = gamma_bn[1*CH32+c] - gamma_bn[2*CH32+c] * sg;
    }
    if (tid >= 32 && tid < 64) {
        int i = tid - 32;
        float suv = 0.f, svv = 0.f;
        for (int c = 0; c < CH8; c++) {
            float se  = eta_bn[0*CH8+c] * rsqrtf(eta_bn[3*CH8+c] + EPSF);
            float smu = mu_bn [0*CH8+c] * rsqrtf(mu_bn [3*CH8+c] + EPSF);
            suv += eta_W[i*CH8+c] * se  * (map_W[1*CH8+c] * s_map);
            svv += mu_W [i*CH8+c] * smu * (map_W[2*CH8+c] * s_map);
        }
        su[i] = suv;
        sv[i] = svv;
    }
    if (tid >= 64 && tid < 64+CH8) {
        int c = tid - 64;
        float sp = point_bn[0*CH8+c] * rsqrtf(point_bn[3*CH8+c] + EPSF);
        stp[c] = point_bn[1*CH8+c] - point_bn[2*CH8+c] * sp;
        #pragma unroll
        for (int i = 0; i < 3; i++)
            sPA[i*CH8+c] = (point_W[(1+i)*CH8+c] + point_W[(7+i)*CH8+c]) * sp;
    }
    if (tid == 96) {
        float k0 = map_bn[1] - map_bn[2] * s_map;
        for (int c = 0; c < CH8; c++) {
            float se  = eta_bn[0*CH8+c] * rsqrtf(eta_bn[3*CH8+c] + EPSF);
            float te  = eta_bn[1*CH8+c] - eta_bn[2*CH8+c] * se;
            float smu = mu_bn [0*CH8+c] * rsqrtf(mu_bn [3*CH8+c] + EPSF);
            float tmu = mu_bn [1*CH8+c] - mu_bn [2*CH8+c] * smu;
            k0 += te  * map_W[1*CH8+c] * s_map;
            k0 += tmu * map_W[2*CH8+c] * s_map;
        }
        sK0 = k0;
    }
    __syncthreads();

    u64 acc0[16], acc1[16];
    const u64* stg2 = (const u64*)stg;
    #pragma unroll
    for (int q = 0; q < 16; q++) { acc0[q] = stg2[q]; acc1[q] = stg2[q]; }

    const float* r0 = &srow[tid * DIM];
    const float* r1 = &srow[(tid + 128) * DIM];
    float pn0[3], pn1[3];
    float e0 = 0.f, e1 = 0.f, m0 = 0.f, m1 = 0.f;

    #pragma unroll
    for (int d = 0; d < 3; d++) {
        float f0 = r0[d], f1 = r1[d];
        pn0[d] = f0; pn1[d] = f1;
        u64 pf0 = pk2(f0, f0), pf1 = pk2(f1, f1);
        const ulonglong2* w4 = (const ulonglong2*)&sW[d*CH32];
        #pragma unroll
        for (int q2 = 0; q2 < 8; q2++) {
            ulonglong2 ww = w4[q2];                 // LDS.128: two weight pairs
            acc0[2*q2]   = ff2(pf0, ww.x, acc0[2*q2]);
            acc1[2*q2]   = ff2(pf1, ww.x, acc1[2*q2]);
            acc0[2*q2+1] = ff2(pf0, ww.y, acc0[2*q2+1]);
            acc1[2*q2+1] = ff2(pf1, ww.y, acc1[2*q2+1]);
        }
    }
    for (int d = 3; d < DIM; d++) {
        float f0 = r0[d], f1 = r1[d];
        float uu = su[d-3], vw = sv[d-3];
        e0 = fmaf(f0, uu, e0); e1 = fmaf(f1, uu, e1);
        m0 = fmaf(f0, vw, m0); m1 = fmaf(f1, vw, m1);
        u64 pf0 = pk2(f0, f0), pf1 = pk2(f1, f1);
        const ulonglong2* w4 = (const ulonglong2*)&sW[d*CH32];
        #pragma unroll
        for (int q2 = 0; q2 < 8; q2++) {
            ulonglong2 ww = w4[q2];                 // LDS.128
            acc0[2*q2]   = ff2(pf0, ww.x, acc0[2*q2]);
            acc1[2*q2]   = ff2(pf1, ww.x, acc1[2*q2]);
            acc0[2*q2+1] = ff2(pf0, ww.y, acc0[2*q2+1]);
            acc1[2*q2+1] = ff2(pf1, ww.y, acc1[2*q2+1]);
        }
    }

    u64 b0p[4], b1p[4];
    {
        const u64* tp2 = (const u64*)stp;
        const u64* pa0 = (const u64*)&sPA[0];
        const u64* pa1 = (const u64*)&sPA[CH8];
        const u64* pa2 = (const u64*)&sPA[2*CH8];
        u64 x0 = pk2(pn0[0], pn0[0]), y0 = pk2(pn0[1], pn0[1]), z0 = pk2(pn0[2], pn0[2]);
        u64 x1 = pk2(pn1[0], pn1[0]), y1 = pk2(pn1[1], pn1[1]), z1 = pk2(pn1[2], pn1[2]);
        #pragma unroll
        for (int q = 0; q < 4; q++) {
            u64 h0 = tp2[q], h1 = tp2[q];
            h0 = ff2(x0, pa0[q], h0); h1 = ff2(x1, pa0[q], h1);
            h0 = ff2(y0, pa1[q], h0); h1 = ff2(y1, pa1[q], h1);
            h0 = ff2(z0, pa2[q], h0); h1 = ff2(z1, pa2[q], h1);
            b0p[q] = h0; b1p[q] = h1;
        }
    }

    int gr0 = R0 + tid, gr1 = R0 + tid + 128;
    ulonglong2* gp0 = (ulonglong2*)&g_gam[(size_t)gr0 * CH32];
    ulonglong2* gp1 = (ulonglong2*)&g_gam[(size_t)gr1 * CH32];
    #pragma unroll
    for (int q = 0; q < 8; q++) {
        gp0[q] = make_ulonglong2(acc0[2*q], acc0[2*q+1]);
        gp1[q] = make_ulonglong2(acc1[2*q], acc1[2*q+1]);
    }
    g_nbr[gr0] = make_float4(pn0[0], pn0[1], pn0[2], m0);
    g_nbr[gr1] = make_float4(pn1[0], pn1[1], pn1[2], m1);
    float K0 = sK0;
    float4* cp0 = &g_ctr[(size_t)gr0*3];
    float4* cp1 = &g_ctr[(size_t)gr1*3];
    {
        float bl, bh;
        up2(b0p[0], bl, bh); float b00 = bl, b01 = bh;
        up2(b0p[1], bl, bh); float b02 = bl, b03 = bh;
        cp0[0] = make_float4(b00, b01, b02, b03);
        up2(b0p[2], bl, bh); b00 = bl; b01 = bh;
        up2(b0p[3], bl, bh); b02 = bl; b03 = bh;
        cp0[1] = make_float4(b00, b01, b02, b03);
        cp0[2] = make_float4(pn0[0], pn0[1], pn0[2], e0 + K0);
        up2(b1p[0], bl, bh); b00 = bl; b01 = bh;
        up2(b1p[1], bl, bh); b02 = bl; b03 = bh;
        cp1[0] = make_float4(b00, b01, b02, b03);
        up2(b1p[2], bl, bh); b00 = bl; b01 = bh;
        up2(b1p[3], bl, bh); b02 = bl; b03 = bh;
        cp1[1] = make_float4(b00, b01, b02, b03);
        cp1[2] = make_float4(pn1[0], pn1[1], pn1[2], e1 + K0);
    }

    // PDL: this block's pass-1 data is globally visible; allow pass2 launch.
    cudaTriggerProgrammaticLaunchCompletion();
}

// ---------------------------------------------------------------------------
// Pass 2: warp = 16 points. Nbr gathers via cp.async (MLP kept, 32 regs
// freed) into a smem buffer UNIONed with the m-matrix (nbr dead after
// phase A, m born in phase B). 5 blocks/SM. __stcs output stores.
// ---------------------------------------------------------------------------
#define NPAIR 8
#define SMSTR 20   // padded m-row stride (floats)

__global__ void __launch_bounds__(128, 5) pass2_kernel(
    const void* __restrict__ idx_raw,
    const float* __restrict__ fcW, float* __restrict__ out,
    const float* __restrict__ point_W, const float* __restrict__ point_bn,
    const float* __restrict__ map_W,   const float* __restrict__ map_bn)
{
    __shared__ __align__(16) float4 sfc[CH32*32];       // fc_W (32x128) = 16 KB
    // union: phase A = nbr staging float4[8][32] (4 KB/warp);
    //        phase B/fc = m matrix float[32][SMSTR] (2.5 KB/warp)
    __shared__ __align__(16) char  suni[4][4096];       // 16 KB
    __shared__ __align__(16) uint2 sjg[4][NPAIR][36];   // (j,g), stride-18/half
    __shared__ __align__(16) float4 sctr[4][48];        // ctr records, 3 KB
    __shared__ __align__(16) float  sw0[CH8], sPB[3*CH8];
    __shared__ float smw[CH8];
    __shared__ int   sIs32;

    int tid = threadIdx.x;
    // ---- prologue: independent of pass1 output (overlaps under PDL) ----
    const float4* fsrc = (const float4*)fcW;
    #pragma unroll
    for (int i = 0; i < 8; i++) sfc[tid + 128*i] = fsrc[tid + 128*i];

    if (tid < 32) {
        const long long* i64 = (const long long*)idx_raw;
        long long v = i64[tid];
        unsigned bad = __ballot_sync(0xffffffffu, v < 0 || v >= NPTS);
        if (tid == 0) sIs32 = bad ? 1 : 0;
        float s_map = map_bn[0] * rsqrtf(map_bn[3] + EPSF);
        if (tid < CH8) {
            int c = tid;
            float sp = point_bn[0*CH8+c] * rsqrtf(point_bn[3*CH8+c] + EPSF);
            sw0[c] = point_W[0*CH8+c] * sp;
            #pragma unroll
            for (int i = 0; i < 3; i++)
                sPB[i*CH8+c] = (point_W[(4+i)*CH8+c] - point_W[(7+i)*CH8+c]) * sp;
            smw[c] = map_W[c] * s_map;
        }
    }
    __syncthreads();

    // idx stride trick: values in [0,N) => low int32 word IS the value for
    // either dtype (little-endian). One load path, uniform stride.
    const int istride = sIs32 ? 4 : 8;
    const char* ibase = (const char*)idx_raw;

    u64 w02[4], PB0p[4], PB1p[4], PB2p[4];
    float mwr[CH8];
    {
        const u64* a  = (const u64*)sw0;
        const u64* b0 = (const u64*)&sPB[0];
        const u64* b1 = (const u64*)&sPB[CH8];
        const u64* b2 = (const u64*)&sPB[2*CH8];
        #pragma unroll
        for (int q = 0; q < 4; q++) {
            w02[q] = a[q]; PB0p[q] = b0[q]; PB1p[q] = b1[q]; PB2p[q] = b2[q];
        }
        #pragma unroll
        for (int c = 0; c < CH8; c++) mwr[c] = smw[c];
    }

    int lane = tid & 31;
    int l16  = lane & 15;
    int half = lane >> 4;                            // 0 or 1
    int w    = tid >> 5;                             // warp in block
    int p0   = (blockIdx.x * 4 + w) * 16;            // 16 points per warp

    float4* snbr_w = (float4*)suni[w];               // [NPAIR][32]
    float*  sm_w   = (float*)suni[w];                // [CH32][SMSTR]

    // idx loads (kernel input — legal pre-sync, deep MLP)
    int jv[NPAIR];
    #pragma unroll
    for (int pair = 0; pair < NPAIR; pair++) {
        int pM = p0 + pair*2 + half;
        size_t off = (size_t)pM * KNN + l16;
        int v = *(const int*)(ibase + off * istride);
        jv[pair] = (pM & ~(NPTS - 1)) + v;
    }

    // ---- wait for pass1 data (PDL acquire) ----
    cudaGridDependencySynchronize();

    // ---- nbr gathers via cp.async: 8-deep MLP with zero register cost ----
    #pragma unroll
    for (int pair = 0; pair < NPAIR; pair++) {
        unsigned sdst = (unsigned)__cvta_generic_to_shared(&snbr_w[pair*32 + lane]);
        const char* gsrc = (const char*)g_nbr + ((size_t)(unsigned)jv[pair] << 4);
        asm volatile("cp.async.cg.shared.global [%0], [%1], 16;"
                     :: "r"(sdst), "l"(gsrc) : "memory");
    }
    asm volatile("cp.async.commit_group;" ::: "memory");

    // ---- ctr stage overlaps the async copies ----
    const float4* cbase = &g_ctr[(size_t)p0 * 3];
    float4 cA = cbase[lane];
    float4 cB = cbase[32 + (lane & 15)];
    sctr[w][lane] = cA;
    if (lane < 16) sctr[w][32 + lane] = cB;

    asm volatile("cp.async.wait_group 0;" ::: "memory");
    __syncwarp();

    // ---- phase A: compute g for all 8 phases, stage (j,g) ----
    #pragma unroll
    for (int pair = 0; pair < NPAIR; pair++) {
        int lp = pair*2 + half;                      // local point 0..15
        float4 cb0 = sctr[w][lp*3 + 0];
        float4 cb1 = sctr[w][lp*3 + 1];
        float4 cpf = sctr[w][lp*3 + 2];              // {px,py,pz,em+K0}
        u64 base2[4] = { pk2(cb0.x, cb0.y), pk2(cb0.z, cb0.w),
                         pk2(cb1.x, cb1.y), pk2(cb1.z, cb1.w) };

        float4 a = snbr_w[pair*32 + lane];
        float dx = cpf.x - a.x, dy = cpf.y - a.y, dz = cpf.z - a.z;
        float t  = fmaf(dx, dx, fmaf(dy, dy, dz*dz));   // |p-pn|^2

        u64 tt = pk2(t, t);
        u64 ax = pk2(a.x, a.x), ay = pk2(a.y, a.y), az = pk2(a.z, a.z);
        float pt = 0.f;
        #pragma unroll
        for (int q = 0; q < 4; q++) {
            u64 h = base2[q];
            h = ff2(w02[q],  tt, h);
            h = ff2(ax, PB0p[q], h);
            h = ff2(ay, PB1p[q], h);
            h = ff2(az, PB2p[q], h);
            float hl, hh; up2(h, hl, hh);
            pt = fmaf(fmaxf(hl, 0.f), mwr[2*q],   pt);
            pt = fmaf(fmaxf(hh, 0.f), mwr[2*q+1], pt);
        }
        float g = fmaxf(pt + cpf.w + a.w, 0.f);          // relu(map bn)
        sjg[w][pair][18*half + l16] = make_uint2((unsigned)jv[pair], __float_as_uint(g));
    }
    __syncwarp();

    // ---- phase B: gam gather + max, transpose, write m to smem ----
    // (snbr is dead now; sm_w reuses the same bytes)
    int c0 = l16;
    #pragma unroll
    for (int pair = 0; pair < NPAIR; pair++) {
        const uint4* jg4 = (const uint4*)&sjg[w][pair][18*half];
        float alo = -3.402823466e38f, ahi = -3.402823466e38f;
        #pragma unroll
        for (int k2 = 0; k2 < KNN/2; k2++) {
            uint4 jg = jg4[k2];                     // neighbors 2k2, 2k2+1
            u64 v0 = *(const u64*)((const char*)g_gam + (((size_t)jg.x << 7) + ((unsigned)c0 << 3)));
            u64 v1 = *(const u64*)((const char*)g_gam + (((size_t)jg.z << 7) + ((unsigned)c0 << 3)));
            float g0 = __uint_as_float(jg.y);
            float g1 = __uint_as_float(jg.w);
            u64 q0 = fm2(v0, pk2(g0, g0));
            u64 q1 = fm2(v1, pk2(g1, g1));
            float q0l, q0h, q1l, q1h;
            up2(q0, q0l, q0h); up2(q1, q1l, q1h);
            alo = fmaxf(alo, fmaxf(q0l, q1l));
            ahi = fmaxf(ahi, fmaxf(q0h, q1h));
        }
        int srcl = lane >> 1;
        float vl0 = __shfl_sync(0xffffffffu, alo, srcl);
        float vh0 = __shfl_sync(0xffffffffu, ahi, srcl);
        float vl1 = __shfl_sync(0xffffffffu, alo, srcl + 16);
        float vh1 = __shfl_sync(0xffffffffu, ahi, srcl + 16);
        float mp0 = (lane & 1) ? vh0 : vl0;
        float mp1 = (lane & 1) ? vh1 : vl1;
        *(float2*)&sm_w[lane*SMSTR + 2*pair] = make_float2(mp0, mp1);
    }
    __syncwarp();

    // ---- fc for 16 points: one sfc sweep, 8 point-pair f32x2 accumulators ----
    u64 accx[NPAIR], accy[NPAIR], accz[NPAIR], accw[NPAIR];
    #pragma unroll
    for (int p = 0; p < NPAIR; p++) { accx[p] = 0; accy[p] = 0; accz[p] = 0; accw[p] = 0; }
    #pragma unroll
    for (int c = 0; c < CH32; c++) {
        float4 wv = sfc[c*32 + lane];
        float4 ma = *(const float4*)&sm_w[c*SMSTR + 0];
        float4 mb = *(const float4*)&sm_w[c*SMSTR + 4];
        float4 mc = *(const float4*)&sm_w[c*SMSTR + 8];
        float4 md = *(const float4*)&sm_w[c*SMSTR + 12];
        u64 wxx = pk2(wv.x, wv.x), wyy = pk2(wv.y, wv.y);
        u64 wzz = pk2(wv.z, wv.z), www = pk2(wv.w, wv.w);
        u64 mp[NPAIR] = {pk2(ma.x, ma.y), pk2(ma.z, ma.w),
                         pk2(mb.x, mb.y), pk2(mb.z, mb.w),
                         pk2(mc.x, mc.y), pk2(mc.z, mc.w),
                         pk2(md.x, md.y), pk2(md.z, md.w)};
        #pragma unroll
        for (int p = 0; p < NPAIR; p++) {
            accx[p] = ff2(mp[p], wxx, accx[p]);
            accy[p] = ff2(mp[p], wyy, accy[p]);
            accz[p] = ff2(mp[p], wzz, accz[p]);
            accw[p] = ff2(mp[p], www, accw[p]);
        }
    }
    // streaming stores: out is write-once — keep gather tables L2-resident.
    float4* op = (float4*)out + (size_t)p0 * 32 + lane;
    #pragma unroll
    for (int p = 0; p < NPAIR; p++) {
        float x0, x1, y0, y1, z0, z1, w0, w1;
        up2(accx[p], x0, x1); up2(accy[p], y0, y1);
        up2(accz[p], z0, z1); up2(accw[p], w0, w1);
        __stcs(&op[(2*p)*32],   make_float4(x0, y0, z0, w0));
        __stcs(&op[(2*p+1)*32], make_float4(x1, y1, z1, w1));
    }
}

extern "C" void kernel_launch(void* const* d_in, const int* in_sizes, int n_in,
                              void* d_out, int out_size)
{
    const float* feats    = (const float*)d_in[0];
    const void*  idx_raw  = (const void*)d_in[1];
    const float* point_W  = (const float*)d_in[2];
    const float* point_bn = (const float*)d_in[3];
    const float* eta_W    = (const float*)d_in[4];
    const float* eta_bn   = (const float*)d_in[5];
    const float* mu_W     = (const float*)d_in[6];
    const float* mu_bn    = (const float*)d_in[7];
    const float* gamma_W  = (const float*)d_in[8];
    const float* gamma_bn = (const float*)d_in[9];
    const float* map_W    = (const float*)d_in[10];
    const float* map_bn   = (const float*)d_in[11];
    const float* fc_W     = (const float*)d_in[12];
    float* out = (float*)d_out;

    pass1_kernel<<<ROWS/256, 128>>>(feats, point_W, point_bn, eta_W, eta_bn,
                                    mu_W, mu_bn, gamma_W, gamma_bn,
                                    map_W, map_bn);

    // pass2 with programmatic dependent launch: prologue overlaps pass1 tail.
    cudaLaunchConfig_t cfg = {};
    cfg.gridDim  = dim3(ROWS/64);
    cfg.blockDim = dim3(128);
    cfg.dynamicSmemBytes = 0;
    cfg.stream = 0;
    cudaLaunchAttribute attrs[1];
    attrs[0].id = cudaLaunchAttributeProgrammaticStreamSerialization;
    attrs[0].val.programmaticStreamSerializationAllowed = 1;
    cfg.attrs = attrs;
    cfg.numAttrs = 1;
    cudaLaunchKernelEx(&cfg, pass2_kernel,
                       (const void*)idx_raw, fc_W, out,
                       point_W, point_bn, map_W, map_bn);
}